// round 1
// baseline (speedup 1.0000x reference)
#include <cuda_runtime.h>
#include <cstdint>

#define BB 512
#define TT 1024
#define NN 64

// One warp per batch element.
// Thread `lane` owns CRF states (columns) j = lane and j = lane+32.
// Recurrence per step:  alpha'_j = x_j + M + log( sum_i exp(alpha_i - M) * E_ij )
// with E = exp(trans) held in registers as packed f32x2 (col pair per entry),
// and p_i = exp(alpha_i - M) exchanged via shared memory, duplicated so the
// inner loop is ld.shared.v2.u64 + fma.rn.f32x2 (2 MACs / instruction).
__global__ __launch_bounds__(32) void crf_fwd_kernel(
    const float* __restrict__ inputs,   // [B, T, N] fp32
    const float* __restrict__ trans,    // [N, N] fp32
    const int*   __restrict__ tags,     // [B, T] int32
    const int*   __restrict__ lens,     // [B] int32
    float*       __restrict__ out)      // [B] fp32
{
    const int b    = blockIdx.x;
    const int lane = threadIdx.x;
    const int L    = lens[b];

    // p exchange buffers, duplicated pairs (p_i, p_i); double buffered.
    __shared__ __align__(16) float2 pp[2][NN];

    // ---- Load trans, build E = exp(trans) packed per column pair ----
    unsigned long long E[NN];
#pragma unroll
    for (int i = 0; i < NN; ++i) {
        float ta = trans[i * NN + lane];
        float tb = trans[i * NN + lane + 32];
        float ea = __expf(ta);
        float eb = __expf(tb);
        asm("mov.b64 %0, {%1, %2};" : "=l"(E[i]) : "f"(ea), "f"(eb));
    }

    // ---- sequence scores (unary + binary), lanes strided over t ----
    const size_t tbase = (size_t)b * TT;
    float sc = 0.f;
    for (int t = lane; t < TT; t += 32) {
        if (t < L) {
            int tg = tags[tbase + t];
            sc += inputs[(tbase + t) * NN + tg];
            if (t >= 1) {
                int tp = tags[tbase + t - 1];
                sc += trans[tp * NN + tg];
            }
        }
    }
#pragma unroll
    for (int o = 16; o; o >>= 1) sc += __shfl_xor_sync(0xffffffffu, sc, o);

    // ---- forward recurrence ----
    const float* xp = inputs + tbase * NN;
    float ax = xp[lane];
    float ay = xp[lane + 32];
    float M  = __shfl_sync(0xffffffffu, ax, 0);

    // one-step-ahead prefetch of x
    float nx1 = 0.f, nx2 = 0.f;
    if (L > 1) { nx1 = xp[NN + lane]; nx2 = xp[NN + 32 + lane]; }

    for (int tt = 1; tt < L; ++tt) {
        const float x1 = nx1, x2 = nx2;
        if (tt + 1 < L) {
            nx1 = xp[(size_t)(tt + 1) * NN + lane];
            nx2 = xp[(size_t)(tt + 1) * NN + 32 + lane];
        }

        // p_i = exp(alpha_i - M), duplicated into shared
        float px = __expf(ax - M);
        float py = __expf(ay - M);
        float2* ppb = pp[tt & 1];
        ppb[lane]      = make_float2(px, px);
        ppb[lane + 32] = make_float2(py, py);
        __syncwarp();

        unsigned s0 = (unsigned)__cvta_generic_to_shared(ppb);
        unsigned long long acc0 = 0ull, acc1 = 0ull, acc2 = 0ull, acc3 = 0ull;
#pragma unroll
        for (int i = 0; i < NN; i += 4) {
            unsigned long long va, vb, vc, vd;
            asm volatile("ld.shared.v2.u64 {%0,%1}, [%2];"
                         : "=l"(va), "=l"(vb) : "r"(s0 + i * 8));
            asm volatile("ld.shared.v2.u64 {%0,%1}, [%2];"
                         : "=l"(vc), "=l"(vd) : "r"(s0 + i * 8 + 16));
            asm("fma.rn.f32x2 %0, %1, %2, %0;" : "+l"(acc0) : "l"(E[i])     , "l"(va));
            asm("fma.rn.f32x2 %0, %1, %2, %0;" : "+l"(acc1) : "l"(E[i + 1]) , "l"(vb));
            asm("fma.rn.f32x2 %0, %1, %2, %0;" : "+l"(acc2) : "l"(E[i + 2]) , "l"(vc));
            asm("fma.rn.f32x2 %0, %1, %2, %0;" : "+l"(acc3) : "l"(E[i + 3]) , "l"(vd));
        }
        asm("add.rn.f32x2 %0, %0, %1;" : "+l"(acc0) : "l"(acc1));
        asm("add.rn.f32x2 %0, %0, %1;" : "+l"(acc2) : "l"(acc3));
        asm("add.rn.f32x2 %0, %0, %1;" : "+l"(acc0) : "l"(acc2));
        float gx, gy;
        asm("mov.b64 {%0,%1}, %2;" : "=f"(gx), "=f"(gy) : "l"(acc0));

        ax = x1 + M + __logf(gx);
        ay = x2 + M + __logf(gy);
        M  = __shfl_sync(0xffffffffu, ax, 0);
    }

    // ---- log_norm = M + log(sum exp(alpha - M)) ----
    float e = __expf(ax - M) + __expf(ay - M);
#pragma unroll
    for (int o = 16; o; o >>= 1) e += __shfl_xor_sync(0xffffffffu, e, o);

    if (lane == 0) out[b] = sc - (M + __logf(e));
}

extern "C" void kernel_launch(void* const* d_in, const int* in_sizes, int n_in,
                              void* d_out, int out_size)
{
    const float* inputs = (const float*)d_in[0];
    const float* trans  = (const float*)d_in[1];
    const int*   tags   = (const int*)d_in[2];
    const int*   lens   = (const int*)d_in[3];
    float*       out    = (float*)d_out;

    crf_fwd_kernel<<<BB, 32>>>(inputs, trans, tags, lens, out);
}

// round 2
// speedup vs baseline: 1.4791x; 1.4791x over previous
#include <cuda_runtime.h>
#include <cstdint>

#define BB 512
#define TT 1024
#define NN 64

// One warp per batch element. Thread `lane` owns CRF states (columns)
// j = lane and j = lane + 32.
//
// Linear-domain recurrence with integer-exponent renormalization:
//   q_j(t+1) = exp(x_j(t+1)) * (sum_i q_i(t) * E_ij) * 2^{-e_t}
//   alpha_j(t) = C_t + log q_j(t),  C_{t+1} = C_t + e_t*ln2
// where e_t = float exponent of q_0(t) (read from the broadcast shared load).
// No MUFU log and no shuffle on the serial chain; exp(x) is off-chain.
//
// E = exp(trans) is register-resident, packed over ROW pairs per column:
//   Ea[k] = (E[2k][j], E[2k+1][j]),  Eb[k] = (E[2k][j+32], E[2k+1][j+32])
// so p loads are the plain 256B vector (16 x ld.shared.v2.u64) and each
// loaded u64 feeds one fma.f32x2 per column.
__global__ __launch_bounds__(32, 1) void crf_fwd_kernel(
    const float* __restrict__ inputs,   // [B, T, N] fp32
    const float* __restrict__ trans,    // [N, N] fp32
    const int*   __restrict__ tags,     // [B, T] int32
    const int*   __restrict__ lens,     // [B] int32
    float*       __restrict__ out)      // [B] fp32
{
    const int b    = blockIdx.x;
    const int lane = threadIdx.x;
    const int L    = lens[b];

    __shared__ __align__(16) float pbuf[2][NN];

    // ---- E = exp(trans), packed over row pairs ----
    unsigned long long Ea[NN / 2], Eb[NN / 2];
#pragma unroll
    for (int k = 0; k < NN / 2; ++k) {
        float e0 = __expf(trans[(2 * k)     * NN + lane]);
        float e1 = __expf(trans[(2 * k + 1) * NN + lane]);
        asm("mov.b64 %0, {%1,%2};" : "=l"(Ea[k]) : "f"(e0), "f"(e1));
        float f0 = __expf(trans[(2 * k)     * NN + lane + 32]);
        float f1 = __expf(trans[(2 * k + 1) * NN + lane + 32]);
        asm("mov.b64 %0, {%1,%2};" : "=l"(Eb[k]) : "f"(f0), "f"(f1));
    }

    // ---- sequence scores (unary + binary), lanes strided over t ----
    const size_t tbase = (size_t)b * TT;
    float sc = 0.f;
    for (int t = lane; t < TT; t += 32) {
        if (t < L) {
            int tg = tags[tbase + t];
            sc += inputs[(tbase + t) * NN + tg];
            if (t >= 1) {
                int tp = tags[tbase + t - 1];
                sc += trans[tp * NN + tg];
            }
        }
    }
#pragma unroll
    for (int o = 16; o; o >>= 1) sc += __shfl_xor_sync(0xffffffffu, sc, o);

    // ---- init: q(0) = exp(x0 - M0), C = M0 ----
    const float* xp = inputs + tbase * NN;
    float x0a = xp[lane];
    float x0b = xp[lane + 32];
    float M0  = __shfl_sync(0xffffffffu, x0a, 0);
    float qa  = __expf(x0a - M0);
    float qb  = __expf(x0b - M0);
    pbuf[0][lane]      = qa;
    pbuf[0][lane + 32] = qb;
    __syncwarp();

    int Ce = 0;

    // x prefetch, depth 2
    float xa1 = 0.f, xb1 = 0.f, xa2 = 0.f, xb2 = 0.f;
    if (L > 1) { xa1 = xp[NN + lane];     xb1 = xp[NN + lane + 32]; }
    if (L > 2) { xa2 = xp[2 * NN + lane]; xb2 = xp[2 * NN + lane + 32]; }

    for (int t = 1; t < L; ++t) {
        // sx = exp(x_t) — independent of the recurrence chain
        const float sxa = __expf(xa1);
        const float sxb = __expf(xb1);
        xa1 = xa2; xb1 = xb2;
        if (t + 2 < L) {
            xa2 = xp[(size_t)(t + 2) * NN + lane];
            xb2 = xp[(size_t)(t + 2) * NN + lane + 32];
        }

        // ---- load full p vector (broadcast), 16 x 16B ----
        const unsigned s0 =
            (unsigned)__cvta_generic_to_shared(&pbuf[(t - 1) & 1][0]);
        unsigned long long v[32];
#pragma unroll
        for (int k = 0; k < 16; ++k) {
            asm volatile("ld.shared.v2.u64 {%0,%1}, [%2];"
                         : "=l"(v[2 * k]), "=l"(v[2 * k + 1])
                         : "r"(s0 + 16 * k));
        }

        // renorm scale from exponent of q_0 (low word of v[0])
        unsigned q0bits;
        asm("mov.b64 {%0,_}, %1;" : "=r"(q0bits) : "l"(v[0]));
        const int e = (int)((q0bits >> 23) & 0xff) - 127;
        Ce += e;
        const float scale = __uint_as_float((unsigned)(127 - e) << 23); // 2^-e
        const float s2a = sxa * scale;
        const float s2b = sxb * scale;

        // ---- 64 x fma.f32x2, 8 accumulator chains ----
        unsigned long long a0 = 0ull, a1 = 0ull, a2 = 0ull, a3 = 0ull;
        unsigned long long b0 = 0ull, b1 = 0ull, b2 = 0ull, b3 = 0ull;
#pragma unroll
        for (int k = 0; k < 32; k += 4) {
            asm("fma.rn.f32x2 %0, %1, %2, %0;" : "+l"(a0) : "l"(Ea[k])     , "l"(v[k]));
            asm("fma.rn.f32x2 %0, %1, %2, %0;" : "+l"(b0) : "l"(Eb[k])     , "l"(v[k]));
            asm("fma.rn.f32x2 %0, %1, %2, %0;" : "+l"(a1) : "l"(Ea[k + 1]) , "l"(v[k + 1]));
            asm("fma.rn.f32x2 %0, %1, %2, %0;" : "+l"(b1) : "l"(Eb[k + 1]) , "l"(v[k + 1]));
            asm("fma.rn.f32x2 %0, %1, %2, %0;" : "+l"(a2) : "l"(Ea[k + 2]) , "l"(v[k + 2]));
            asm("fma.rn.f32x2 %0, %1, %2, %0;" : "+l"(b2) : "l"(Eb[k + 2]) , "l"(v[k + 2]));
            asm("fma.rn.f32x2 %0, %1, %2, %0;" : "+l"(a3) : "l"(Ea[k + 3]) , "l"(v[k + 3]));
            asm("fma.rn.f32x2 %0, %1, %2, %0;" : "+l"(b3) : "l"(Eb[k + 3]) , "l"(v[k + 3]));
        }
        asm("add.rn.f32x2 %0, %0, %1;" : "+l"(a0) : "l"(a1));
        asm("add.rn.f32x2 %0, %0, %1;" : "+l"(a2) : "l"(a3));
        asm("add.rn.f32x2 %0, %0, %1;" : "+l"(b0) : "l"(b1));
        asm("add.rn.f32x2 %0, %0, %1;" : "+l"(b2) : "l"(b3));
        asm("add.rn.f32x2 %0, %0, %1;" : "+l"(a0) : "l"(a2));
        asm("add.rn.f32x2 %0, %0, %1;" : "+l"(b0) : "l"(b2));
        float gal, gah, gbl, gbh;
        asm("mov.b64 {%0,%1}, %2;" : "=f"(gal), "=f"(gah) : "l"(a0));
        asm("mov.b64 {%0,%1}, %2;" : "=f"(gbl), "=f"(gbh) : "l"(b0));

        qa = (gal + gah) * s2a;
        qb = (gbl + gbh) * s2b;

        float* pw = pbuf[t & 1];
        pw[lane]      = qa;
        pw[lane + 32] = qb;
        __syncwarp();
    }

    // ---- log_norm = M0 + Ce*ln2 + log(sum_j q_j) ----
    float s = qa + qb;
#pragma unroll
    for (int o = 16; o; o >>= 1) s += __shfl_xor_sync(0xffffffffu, s, o);

    if (lane == 0) {
        const float log_norm = M0 + (float)Ce * 0.6931471805599453f + __logf(s);
        out[b] = sc - log_norm;
    }
}

extern "C" void kernel_launch(void* const* d_in, const int* in_sizes, int n_in,
                              void* d_out, int out_size)
{
    const float* inputs = (const float*)d_in[0];
    const float* trans  = (const float*)d_in[1];
    const int*   tags   = (const int*)d_in[2];
    const int*   lens   = (const int*)d_in[3];
    float*       out    = (float*)d_out;

    crf_fwd_kernel<<<BB, 32>>>(inputs, trans, tags, lens, out);
}

// round 3
// speedup vs baseline: 1.9230x; 1.3001x over previous
#include <cuda_runtime.h>
#include <cstdint>

#define BB 512
#define TT 1024
#define NN 64
#define WPB 4   // warps (= batches) per block

// One warp per batch element; 4 independent warps per block so the four
// warps land on the four SMSPs (wid % 4). With grid = B/4 = 128 blocks on
// 148 SMs, every SMSP chip-wide runs at most one warp -> no issue-port
// contention between long batches (the R2 bottleneck).
//
// Per-warp algorithm (unchanged from R2): thread `lane` owns columns
// j = lane, lane+32. Linear-domain recurrence with integer-exponent renorm:
//   q_j(t+1) = exp(x_j(t+1)) * (sum_i q_i(t) * E_ij) * 2^{-e_t}
// E = exp(trans) register-resident, packed over ROW pairs, so the p vector
// loads are 16 x ld.shared.v2.u64 and each u64 feeds one fma.f32x2/column.
__global__ __launch_bounds__(32 * WPB, 1) void crf_fwd_kernel(
    const float* __restrict__ inputs,   // [B, T, N] fp32
    const float* __restrict__ trans,    // [N, N] fp32
    const int*   __restrict__ tags,     // [B, T] int32
    const int*   __restrict__ lens,     // [B] int32
    float*       __restrict__ out)      // [B] fp32
{
    const int lane = threadIdx.x & 31;
    const int wid  = threadIdx.x >> 5;
    const int b    = blockIdx.x * WPB + wid;
    const int L    = lens[b];

    __shared__ __align__(16) float pbuf[WPB][2][NN];

    // ---- E = exp(trans), packed over row pairs ----
    unsigned long long Ea[NN / 2], Eb[NN / 2];
#pragma unroll
    for (int k = 0; k < NN / 2; ++k) {
        float e0 = __expf(trans[(2 * k)     * NN + lane]);
        float e1 = __expf(trans[(2 * k + 1) * NN + lane]);
        asm("mov.b64 %0, {%1,%2};" : "=l"(Ea[k]) : "f"(e0), "f"(e1));
        float f0 = __expf(trans[(2 * k)     * NN + lane + 32]);
        float f1 = __expf(trans[(2 * k + 1) * NN + lane + 32]);
        asm("mov.b64 %0, {%1,%2};" : "=l"(Eb[k]) : "f"(f0), "f"(f1));
    }

    // ---- sequence scores (unary + binary), lanes strided over t ----
    const size_t tbase = (size_t)b * TT;
    float sc = 0.f;
    for (int t = lane; t < TT; t += 32) {
        if (t < L) {
            int tg = tags[tbase + t];
            sc += inputs[(tbase + t) * NN + tg];
            if (t >= 1) {
                int tp = tags[tbase + t - 1];
                sc += trans[tp * NN + tg];
            }
        }
    }
#pragma unroll
    for (int o = 16; o; o >>= 1) sc += __shfl_xor_sync(0xffffffffu, sc, o);

    // ---- init: q(0) = exp(x0 - M0), C = M0 ----
    const float* xp = inputs + tbase * NN;
    float x0a = xp[lane];
    float x0b = xp[lane + 32];
    float M0  = __shfl_sync(0xffffffffu, x0a, 0);
    float qa  = __expf(x0a - M0);
    float qb  = __expf(x0b - M0);
    pbuf[wid][0][lane]      = qa;
    pbuf[wid][0][lane + 32] = qb;
    __syncwarp();

    int Ce = 0;

    // x prefetch, depth 2
    float xa1 = 0.f, xb1 = 0.f, xa2 = 0.f, xb2 = 0.f;
    if (L > 1) { xa1 = xp[NN + lane];     xb1 = xp[NN + lane + 32]; }
    if (L > 2) { xa2 = xp[2 * NN + lane]; xb2 = xp[2 * NN + lane + 32]; }

    for (int t = 1; t < L; ++t) {
        // sx = exp(x_t) — independent of the recurrence chain
        const float sxa = __expf(xa1);
        const float sxb = __expf(xb1);
        xa1 = xa2; xb1 = xb2;
        if (t + 2 < L) {
            xa2 = xp[(size_t)(t + 2) * NN + lane];
            xb2 = xp[(size_t)(t + 2) * NN + lane + 32];
        }

        // ---- load full p vector (broadcast), 16 x 16B ----
        const unsigned s0 =
            (unsigned)__cvta_generic_to_shared(&pbuf[wid][(t - 1) & 1][0]);
        unsigned long long v[32];
#pragma unroll
        for (int k = 0; k < 16; ++k) {
            asm volatile("ld.shared.v2.u64 {%0,%1}, [%2];"
                         : "=l"(v[2 * k]), "=l"(v[2 * k + 1])
                         : "r"(s0 + 16 * k));
        }

        // renorm scale from exponent of q_0 (low word of v[0])
        unsigned q0bits;
        asm("mov.b64 {%0,_}, %1;" : "=r"(q0bits) : "l"(v[0]));
        const int e = (int)((q0bits >> 23) & 0xff) - 127;
        Ce += e;
        const float scale = __uint_as_float((unsigned)(127 - e) << 23); // 2^-e
        const float s2a = sxa * scale;
        const float s2b = sxb * scale;

        // ---- 64 x fma.f32x2, 8 accumulator chains ----
        unsigned long long a0 = 0ull, a1 = 0ull, a2 = 0ull, a3 = 0ull;
        unsigned long long b0 = 0ull, b1 = 0ull, b2 = 0ull, b3 = 0ull;
#pragma unroll
        for (int k = 0; k < 32; k += 4) {
            asm("fma.rn.f32x2 %0, %1, %2, %0;" : "+l"(a0) : "l"(Ea[k])     , "l"(v[k]));
            asm("fma.rn.f32x2 %0, %1, %2, %0;" : "+l"(b0) : "l"(Eb[k])     , "l"(v[k]));
            asm("fma.rn.f32x2 %0, %1, %2, %0;" : "+l"(a1) : "l"(Ea[k + 1]) , "l"(v[k + 1]));
            asm("fma.rn.f32x2 %0, %1, %2, %0;" : "+l"(b1) : "l"(Eb[k + 1]) , "l"(v[k + 1]));
            asm("fma.rn.f32x2 %0, %1, %2, %0;" : "+l"(a2) : "l"(Ea[k + 2]) , "l"(v[k + 2]));
            asm("fma.rn.f32x2 %0, %1, %2, %0;" : "+l"(b2) : "l"(Eb[k + 2]) , "l"(v[k + 2]));
            asm("fma.rn.f32x2 %0, %1, %2, %0;" : "+l"(a3) : "l"(Ea[k + 3]) , "l"(v[k + 3]));
            asm("fma.rn.f32x2 %0, %1, %2, %0;" : "+l"(b3) : "l"(Eb[k + 3]) , "l"(v[k + 3]));
        }
        asm("add.rn.f32x2 %0, %0, %1;" : "+l"(a0) : "l"(a1));
        asm("add.rn.f32x2 %0, %0, %1;" : "+l"(a2) : "l"(a3));
        asm("add.rn.f32x2 %0, %0, %1;" : "+l"(b0) : "l"(b1));
        asm("add.rn.f32x2 %0, %0, %1;" : "+l"(b2) : "l"(b3));
        asm("add.rn.f32x2 %0, %0, %1;" : "+l"(a0) : "l"(a2));
        asm("add.rn.f32x2 %0, %0, %1;" : "+l"(b0) : "l"(b2));
        float gal, gah, gbl, gbh;
        asm("mov.b64 {%0,%1}, %2;" : "=f"(gal), "=f"(gah) : "l"(a0));
        asm("mov.b64 {%0,%1}, %2;" : "=f"(gbl), "=f"(gbh) : "l"(b0));

        qa = (gal + gah) * s2a;
        qb = (gbl + gbh) * s2b;

        float* pw = pbuf[wid][t & 1];
        pw[lane]      = qa;
        pw[lane + 32] = qb;
        __syncwarp();
    }

    // ---- log_norm = M0 + Ce*ln2 + log(sum_j q_j) ----
    float s = qa + qb;
#pragma unroll
    for (int o = 16; o; o >>= 1) s += __shfl_xor_sync(0xffffffffu, s, o);

    if (lane == 0) {
        const float log_norm = M0 + (float)Ce * 0.6931471805599453f + __logf(s);
        out[b] = sc - log_norm;
    }
}

extern "C" void kernel_launch(void* const* d_in, const int* in_sizes, int n_in,
                              void* d_out, int out_size)
{
    const float* inputs = (const float*)d_in[0];
    const float* trans  = (const float*)d_in[1];
    const int*   tags   = (const int*)d_in[2];
    const int*   lens   = (const int*)d_in[3];
    float*       out    = (float*)d_out;

    crf_fwd_kernel<<<BB / WPB, 32 * WPB>>>(inputs, trans, tags, lens, out);
}